// round 4
// baseline (speedup 1.0000x reference)
#include <cuda_runtime.h>
#include <cuda_fp16.h>
#include <cstdint>

#define NN 100000
#define NN_PAD 100096          // 782 * 128
#define NE 1600000
#define SCAN_NB 98             // ceil(NN/1024)

// ---------------- scratch (static __device__ arrays; no allocation) ----------
__device__ uint2  g_f0[NN * 32];      // [N,128] fp16 features buffer A
__device__ uint2  g_f1[NN * 32];      // [N,128] fp16 features buffer B
__device__ int    g_csr[NE];          // src ids grouped by dst
__device__ int    g_rank[NE];         // per-edge rank within its dst bucket
__device__ int    g_outdeg[NN];
__device__ int    g_indeg[NN];
__device__ float  g_ns[NN];
__device__ float  g_nd[NN];
__device__ int    g_rowstart[NN + 1];
__device__ int    g_blocksums[128];
__device__ uint4  g_wt0[256 * 128 / 4];   // [256,128] tf32 bits: [w0 ; rw0]
__device__ uint4  g_wt1[256 * 128 / 4];   // [256,128] tf32 bits: [w1 ; rw1]
__device__ uint4  g_wt2[256 * 64 / 4];    // [256,64]  tf32 bits: [w2 ; rw2]

// ---------------- helpers ----------------------------------------------------
__device__ __forceinline__ uint32_t f2tf(float f) {
    uint32_t u;
    asm("cvt.rna.tf32.f32 %0, %1;" : "=r"(u) : "f"(f));
    return u;
}

__device__ __forceinline__ void mma_tf32(float* c, const uint32_t* a, const uint32_t* b) {
    asm volatile(
        "mma.sync.aligned.m16n8k8.row.col.f32.tf32.tf32.f32 "
        "{%0,%1,%2,%3}, {%4,%5,%6,%7}, {%8,%9}, {%0,%1,%2,%3};\n"
        : "+f"(c[0]), "+f"(c[1]), "+f"(c[2]), "+f"(c[3])
        : "r"(a[0]), "r"(a[1]), "r"(a[2]), "r"(a[3]), "r"(b[0]), "r"(b[1]));
}

__device__ __forceinline__ void cp16(uint32_t dst, const void* src) {
    asm volatile("cp.async.cg.shared.global [%0], [%1], 16;\n" :: "r"(dst), "l"(src));
}
__device__ __forceinline__ void cpcommit() {
    asm volatile("cp.async.commit_group;\n");
}
template <int N>
__device__ __forceinline__ void cpwait() {
    asm volatile("cp.async.wait_group %0;\n" :: "n"(N));
}

// ---------------- fused prep: weights->tf32, zero degs, raw_x->fp16 ----------
__global__ void k_prep(const float4* __restrict__ raw_x,
                       const float* __restrict__ w0, const float* __restrict__ rw0,
                       const float* __restrict__ w1, const float* __restrict__ rw1,
                       const float* __restrict__ w2, const float* __restrict__ rw2) {
    int i = blockIdx.x * blockDim.x + threadIdx.x;
    if (i < 32768) {
        int r = i >> 7, c = i & 127;
        float v = (r < 128) ? w0[r * 128 + c] : rw0[(r - 128) * 128 + c];
        ((uint32_t*)g_wt0)[i] = f2tf(v);
    } else if (i < 65536) {
        int j = i - 32768;
        int r = j >> 7, c = j & 127;
        float v = (r < 128) ? w1[r * 128 + c] : rw1[(r - 128) * 128 + c];
        ((uint32_t*)g_wt1)[j] = f2tf(v);
    } else if (i < 81920) {
        int j = i - 65536;
        int r = j >> 6, c = j & 63;
        float v = (r < 128) ? w2[r * 64 + c] : rw2[(r - 128) * 64 + c];
        ((uint32_t*)g_wt2)[j] = f2tf(v);
    } else if (i < 106920) {
        ((int4*)g_outdeg)[i - 81920] = make_int4(0, 0, 0, 0);
    } else if (i < 131920) {
        ((int4*)g_indeg)[i - 106920] = make_int4(0, 0, 0, 0);
    } else if (i < 3331920) {
        int j = i - 131920;                 // float4 index == uint2 index
        float4 v = raw_x[j];
        __half2 h0 = __floats2half2_rn(v.x, v.y);
        __half2 h1 = __floats2half2_rn(v.z, v.w);
        uint2 u;
        u.x = *reinterpret_cast<uint32_t*>(&h0);
        u.y = *reinterpret_cast<uint32_t*>(&h1);
        g_f0[j] = u;
    }
}

// ---------------- degree count + per-edge dst rank ----------------------------
__global__ void k_deg(const int4* __restrict__ src4, const int4* __restrict__ dst4) {
    int e = blockIdx.x * blockDim.x + threadIdx.x;
    if (e < NE / 4) {
        int4 s = src4[e];
        int4 d = dst4[e];
        atomicAdd(&g_outdeg[s.x], 1); atomicAdd(&g_outdeg[s.y], 1);
        atomicAdd(&g_outdeg[s.z], 1); atomicAdd(&g_outdeg[s.w], 1);
        int4 r;
        r.x = atomicAdd(&g_indeg[d.x], 1);
        r.y = atomicAdd(&g_indeg[d.y], 1);
        r.z = atomicAdd(&g_indeg[d.z], 1);
        r.w = atomicAdd(&g_indeg[d.w], 1);
        ((int4*)g_rank)[e] = r;
    }
}

// exclusive scan of g_indeg: per-block scan + blocksums
__global__ void k_scan1() {
    __shared__ int sh[1024];
    int t = threadIdx.x;
    int i = blockIdx.x * 1024 + t;
    int v = (i < NN) ? g_indeg[i] : 0;
    sh[t] = v;
    __syncthreads();
    #pragma unroll
    for (int off = 1; off < 1024; off <<= 1) {
        int add = (t >= off) ? sh[t - off] : 0;
        __syncthreads();
        sh[t] += add;
        __syncthreads();
    }
    if (i < NN) g_rowstart[i] = sh[t] - v;  // exclusive within block
    if (t == 1023) g_blocksums[blockIdx.x] = sh[1023];
}

// apply block offsets + compute norms (Hillis-Steele over blocksums)
__global__ void k_scan23() {
    __shared__ int sh[128];
    int t = threadIdx.x;
    int v = (t < SCAN_NB) ? g_blocksums[t] : 0;
    if (t < 128) sh[t] = v;
    __syncthreads();
    #pragma unroll
    for (int off = 1; off < 128; off <<= 1) {
        int add = (t < 128 && t >= off) ? sh[t - off] : 0;
        __syncthreads();
        if (t < 128) sh[t] += add;
        __syncthreads();
    }
    int i = blockIdx.x * blockDim.x + t;
    if (i < NN) {
        int b = i >> 10;
        int pre = (b > 0) ? sh[b - 1] : 0;   // inclusive[b-1] == exclusive[b]
        g_rowstart[i] += pre;
        g_ns[i] = rsqrtf(fmaxf((float)g_outdeg[i], 1.0f));
        g_nd[i] = rsqrtf(fmaxf((float)g_indeg[i], 1.0f));
    }
    if (i == 0) g_rowstart[NN] = NE;
}

// atomic-free CSR fill: pos = rowstart[dst] + rank
__global__ void k_csr(const int4* __restrict__ src4, const int4* __restrict__ dst4) {
    int e = blockIdx.x * blockDim.x + threadIdx.x;
    if (e < NE / 4) {
        int4 s = src4[e];
        int4 d = dst4[e];
        int4 r = ((const int4*)g_rank)[e];
        g_csr[g_rowstart[d.x] + r.x] = s.x;
        g_csr[g_rowstart[d.y] + r.y] = s.y;
        g_csr[g_rowstart[d.z] + r.z] = s.z;
        g_csr[g_rowstart[d.w] + r.w] = s.w;
    }
}

// ---------------- fused SpMM + GEMM layer kernel ------------------------------
// Phase 1: 16 warps gather/aggregate 128 nodes -> smem A tile [128,256] tf32
//          A = [ (sum x_j ns_j)*nd | sum x_j ]
// Phase 2: C[128,BN] = A @ Bw[256,BN] + bias  (tf32 mma, B via cp.async)
__device__ __forceinline__ void acc_edge(uint2 u, float n, float* a1, float* a2) {
    float2 f0 = __half22float2(*reinterpret_cast<__half2*>(&u.x));
    float2 f1 = __half22float2(*reinterpret_cast<__half2*>(&u.y));
    a2[0] += f0.x; a2[1] += f0.y; a2[2] += f1.x; a2[3] += f1.y;
    a1[0] = fmaf(f0.x, n, a1[0]); a1[1] = fmaf(f0.y, n, a1[1]);
    a1[2] = fmaf(f1.x, n, a1[2]); a1[3] = fmaf(f1.y, n, a1[3]);
}

template <int BN, bool RELU, bool HALFOUT>
__global__ __launch_bounds__(512) void k_fused(
    const uint2* __restrict__ x, const uint32_t* __restrict__ Bw,
    const float* __restrict__ bias, void* __restrict__ Cv)
{
    constexpr int BM = 128, BK = 32, K = 256;
    constexpr int AS = 260;            // A tile stride (words), pad 4
    constexpr int BS = BN + 8;         // B tile stride
    constexpr int NT = BN / 32;        // 8-col mma tiles per warp (warp n = BN/4)
    constexpr int BBUF = BK * BS;
    constexpr int NKC = K / BK;        // 8 K-chunks

    extern __shared__ uint32_t dyn[];
    uint32_t* sA = dyn;                          // BM * AS
    uint32_t* sB = dyn + BM * AS;                // 2 * BBUF
    const uint32_t saddrB = (uint32_t)__cvta_generic_to_shared(sB);

    const int tid  = threadIdx.x;
    const int warp = tid >> 5, lane = tid & 31;
    const int grp  = lane >> 2, tig = lane & 3;
    const int blockRow = blockIdx.x * BM;

    auto stageB = [&](int kc, int buf) {
        #pragma unroll
        for (int it = 0; it < (BK * BN / 4) / 512; ++it) {
            int idx = tid + it * 512;
            int r = idx / (BN / 4), c = (idx % (BN / 4)) * 4;
            cp16(saddrB + (uint32_t)(buf * BBUF + r * BS + c) * 4,
                 Bw + (size_t)(kc * BK + r) * BN + c);
        }
        cpcommit();
    };

    // prefetch first two B chunks; they land while we do the gather phase
    stageB(0, 0);
    stageB(1, 1);

    // ---------------- phase 1: spmm into smem A tile -------------------------
    #pragma unroll 1
    for (int i = 0; i < 8; ++i) {
        int node = blockRow + warp * 8 + i;
        float a1[4] = {0.f, 0.f, 0.f, 0.f};
        float a2[4] = {0.f, 0.f, 0.f, 0.f};
        float nd = 0.f;
        if (node < NN) {
            int s = g_rowstart[node];
            int e = g_rowstart[node + 1];
            nd = g_nd[node];
            int p = s;
            for (; p + 7 < e; p += 8) {
                int   j[8];
                float n[8];
                uint2 u[8];
                #pragma unroll
                for (int q = 0; q < 8; ++q) j[q] = g_csr[p + q];
                #pragma unroll
                for (int q = 0; q < 8; ++q) n[q] = g_ns[j[q]];
                #pragma unroll
                for (int q = 0; q < 8; ++q) u[q] = x[(size_t)j[q] * 32 + lane];
                #pragma unroll
                for (int q = 0; q < 8; ++q) acc_edge(u[q], n[q], a1, a2);
            }
            for (; p < e; ++p) {
                int j0 = g_csr[p];
                float n0 = g_ns[j0];
                uint2 u0 = x[(size_t)j0 * 32 + lane];
                acc_edge(u0, n0, a1, a2);
            }
        }
        uint32_t* rowp = sA + (warp * 8 + i) * AS;
        uint4 o1, o2;
        o1.x = f2tf(a1[0] * nd); o1.y = f2tf(a1[1] * nd);
        o1.z = f2tf(a1[2] * nd); o1.w = f2tf(a1[3] * nd);
        o2.x = f2tf(a2[0]); o2.y = f2tf(a2[1]);
        o2.z = f2tf(a2[2]); o2.w = f2tf(a2[3]);
        *reinterpret_cast<uint4*>(rowp + 4 * lane)       = o1;
        *reinterpret_cast<uint4*>(rowp + 128 + 4 * lane) = o2;
    }

    // ---------------- phase 2: GEMM ------------------------------------------
    // warp grid 4x4: warp tile 32(m) x BN/4(n)
    const int wm = (warp >> 2) * 32;
    const int wn = (warp & 3) * (BN / 4);

    float acc[2][NT][4];
    #pragma unroll
    for (int mt = 0; mt < 2; mt++)
        #pragma unroll
        for (int nt = 0; nt < NT; nt++)
            #pragma unroll
            for (int r = 0; r < 4; r++) acc[mt][nt][r] = 0.f;

    #pragma unroll
    for (int kc = 0; kc < NKC; ++kc) {
        int buf = kc & 1;
        cpwait<1>();
        __syncthreads();   // (first iteration also closes phase 1)

        const uint32_t* cB = sB + buf * BBUF;
        #pragma unroll
        for (int ks = 0; ks < 4; ++ks) {
            uint32_t af[2][4];
            #pragma unroll
            for (int mt = 0; mt < 2; mt++) {
                int row = wm + mt * 16 + grp;
                int ko = kc * BK + ks * 8 + tig;
                af[mt][0] = sA[row * AS + ko];
                af[mt][1] = sA[(row + 8) * AS + ko];
                af[mt][2] = sA[row * AS + ko + 4];
                af[mt][3] = sA[(row + 8) * AS + ko + 4];
            }
            uint32_t bf[NT][2];
            #pragma unroll
            for (int nt = 0; nt < NT; nt++) {
                int col = wn + nt * 8 + grp;
                bf[nt][0] = cB[(ks * 8 + tig) * BS + col];
                bf[nt][1] = cB[(ks * 8 + tig + 4) * BS + col];
            }
            #pragma unroll
            for (int mt = 0; mt < 2; mt++)
                #pragma unroll
                for (int nt = 0; nt < NT; nt++)
                    mma_tf32(acc[mt][nt], af[mt], bf[nt]);
        }
        __syncthreads();
        if (kc + 2 < NKC) stageB(kc + 2, buf);
    }

    // epilogue: bias (+relu), half2 or float2 stores
    #pragma unroll
    for (int mt = 0; mt < 2; ++mt) {
        int r0 = blockRow + wm + mt * 16 + grp;
        int r1 = r0 + 8;
        #pragma unroll
        for (int nt = 0; nt < NT; ++nt) {
            int col = wn + nt * 8 + 2 * tig;
            float b0v = bias[col], b1v = bias[col + 1];
            float v0 = acc[mt][nt][0] + b0v;
            float v1 = acc[mt][nt][1] + b1v;
            float v2 = acc[mt][nt][2] + b0v;
            float v3 = acc[mt][nt][3] + b1v;
            if (RELU) {
                v0 = fmaxf(v0, 0.f); v1 = fmaxf(v1, 0.f);
                v2 = fmaxf(v2, 0.f); v3 = fmaxf(v3, 0.f);
            }
            if (HALFOUT) {
                __half* C = (__half*)Cv;
                if (r0 < NN)
                    *reinterpret_cast<__half2*>(&C[(size_t)r0 * BN + col]) =
                        __floats2half2_rn(v0, v1);
                if (r1 < NN)
                    *reinterpret_cast<__half2*>(&C[(size_t)r1 * BN + col]) =
                        __floats2half2_rn(v2, v3);
            } else {
                float* C = (float*)Cv;
                if (r0 < NN)
                    *reinterpret_cast<float2*>(&C[(size_t)r0 * BN + col]) = make_float2(v0, v1);
                if (r1 < NN)
                    *reinterpret_cast<float2*>(&C[(size_t)r1 * BN + col]) = make_float2(v2, v3);
            }
        }
    }
}

// ---------------- launcher ----------------------------------------------------
extern "C" void kernel_launch(void* const* d_in, const int* in_sizes, int n_in,
                              void* d_out, int out_size) {
    const float* raw_x = (const float*)d_in[0];
    const int*   src   = (const int*)d_in[1];
    const int*   dst   = (const int*)d_in[2];
    const float* w0    = (const float*)d_in[3];
    const float* b0    = (const float*)d_in[4];
    const float* w1    = (const float*)d_in[5];
    const float* b1    = (const float*)d_in[6];
    const float* w2    = (const float*)d_in[7];
    const float* b2    = (const float*)d_in[8];
    const float* rw0   = (const float*)d_in[9];
    const float* rw1   = (const float*)d_in[10];
    const float* rw2   = (const float*)d_in[11];
    float* out = (float*)d_out;

    void *pf0 = nullptr, *pf1 = nullptr;
    void *pw0 = nullptr, *pw1 = nullptr, *pw2 = nullptr;
    cudaGetSymbolAddress(&pf0, g_f0);
    cudaGetSymbolAddress(&pf1, g_f1);
    cudaGetSymbolAddress(&pw0, g_wt0);
    cudaGetSymbolAddress(&pw1, g_wt1);
    cudaGetSymbolAddress(&pw2, g_wt2);

    constexpr int SMEM128 = (128 * 260 + 2 * 32 * 136) * 4;  // 167936
    constexpr int SMEM64  = (128 * 260 + 2 * 32 * 72) * 4;   // 151552
    cudaFuncSetAttribute(k_fused<128, true, true>,
                         cudaFuncAttributeMaxDynamicSharedMemorySize, SMEM128);
    cudaFuncSetAttribute(k_fused<64, false, false>,
                         cudaFuncAttributeMaxDynamicSharedMemorySize, SMEM64);

    const int TB = 256;
    k_prep<<<(3331920 + TB - 1) / TB, TB>>>((const float4*)raw_x,
                                            w0, rw0, w1, rw1, w2, rw2);
    k_deg<<<(NE / 4 + TB - 1) / TB, TB>>>((const int4*)src, (const int4*)dst);
    k_scan1<<<SCAN_NB, 1024>>>();
    k_scan23<<<(NN + TB - 1) / TB, TB>>>();
    k_csr<<<(NE / 4 + TB - 1) / TB, TB>>>((const int4*)src, (const int4*)dst);

    const int BLOCKS = NN_PAD / 128;  // 782

    // layer 1: read g_f0 (x), write g_f1 (h1)
    k_fused<128, true, true><<<BLOCKS, 512, SMEM128>>>(
        (const uint2*)pf0, (const uint32_t*)pw0, b0, pf1);
    // layer 2: read g_f1, write g_f0 (h2)
    k_fused<128, true, true><<<BLOCKS, 512, SMEM128>>>(
        (const uint2*)pf1, (const uint32_t*)pw1, b1, pf0);
    // layer 3: read g_f0, write d_out (fp32)
    k_fused<64, false, false><<<BLOCKS, 512, SMEM64>>>(
        (const uint2*)pf0, (const uint32_t*)pw2, b2, out);
}

// round 5
// speedup vs baseline: 1.6050x; 1.6050x over previous
#include <cuda_runtime.h>
#include <cuda_fp16.h>
#include <cstdint>

#define NN 100000
#define NN_PAD 100096          // 782 * 128
#define NE 1600000
#define SCAN_NB 98             // ceil(NN/1024)

// ---------------- scratch (static __device__ arrays; no allocation) ----------
__device__ __half g_yh[NN_PAD * 256]; // [N,256] fp16: [spmm(x*ns)*nd | spmm(x)]
__device__ uint2  g_f0[NN * 32];      // [N,128] fp16 features buffer A
__device__ uint2  g_f1[NN * 32];      // [N,128] fp16 features buffer B
__device__ int    g_csr[NE];          // src ids grouped by dst
__device__ int    g_rank[NE];         // per-edge rank within its dst bucket
__device__ int    g_outdeg[NN];
__device__ int    g_indeg[NN];
__device__ float  g_ns[NN];
__device__ float  g_nd[NN];
__device__ int    g_rowstart[NN + 1];
__device__ int    g_blocksums[128];
__device__ __half g_wt0[128 * 256];   // [128n][256k] fp16: transposed [w0;rw0]
__device__ __half g_wt1[128 * 256];   // [128n][256k] fp16: transposed [w1;rw1]
__device__ __half g_wt2[64 * 256];    // [64n][256k]  fp16: transposed [w2;rw2]

// ---------------- helpers ----------------------------------------------------
__device__ __forceinline__ void mma_f16(float* c, const uint32_t* a, const uint32_t* b) {
    asm volatile(
        "mma.sync.aligned.m16n8k16.row.col.f32.f16.f16.f32 "
        "{%0,%1,%2,%3}, {%4,%5,%6,%7}, {%8,%9}, {%0,%1,%2,%3};\n"
        : "+f"(c[0]), "+f"(c[1]), "+f"(c[2]), "+f"(c[3])
        : "r"(a[0]), "r"(a[1]), "r"(a[2]), "r"(a[3]), "r"(b[0]), "r"(b[1]));
}

__device__ __forceinline__ void cp16(uint32_t dst, const void* src) {
    asm volatile("cp.async.cg.shared.global [%0], [%1], 16;\n" :: "r"(dst), "l"(src));
}
__device__ __forceinline__ void cpcommit() {
    asm volatile("cp.async.commit_group;\n");
}
template <int N>
__device__ __forceinline__ void cpwait() {
    asm volatile("cp.async.wait_group %0;\n" :: "n"(N));
}

// ---------------- fused prep: weights->fp16 transposed, zero degs, x->fp16 ----
__global__ void k_prep(const float4* __restrict__ raw_x,
                       const float* __restrict__ w0, const float* __restrict__ rw0,
                       const float* __restrict__ w1, const float* __restrict__ rw1,
                       const float* __restrict__ w2, const float* __restrict__ rw2) {
    int i = blockIdx.x * blockDim.x + threadIdx.x;
    if (i < 32768) {
        int k = i >> 7, n = i & 127;
        float v = (k < 128) ? w0[k * 128 + n] : rw0[(k - 128) * 128 + n];
        g_wt0[n * 256 + k] = __float2half(v);
    } else if (i < 65536) {
        int j = i - 32768;
        int k = j >> 7, n = j & 127;
        float v = (k < 128) ? w1[k * 128 + n] : rw1[(k - 128) * 128 + n];
        g_wt1[n * 256 + k] = __float2half(v);
    } else if (i < 81920) {
        int j = i - 65536;
        int k = j >> 6, n = j & 63;
        float v = (k < 128) ? w2[k * 64 + n] : rw2[(k - 128) * 64 + n];
        g_wt2[n * 256 + k] = __float2half(v);
    } else if (i < 106920) {
        ((int4*)g_outdeg)[i - 81920] = make_int4(0, 0, 0, 0);
    } else if (i < 131920) {
        ((int4*)g_indeg)[i - 106920] = make_int4(0, 0, 0, 0);
    } else if (i < 3331920) {
        int j = i - 131920;                 // float4 index == uint2 index
        float4 v = raw_x[j];
        __half2 h0 = __floats2half2_rn(v.x, v.y);
        __half2 h1 = __floats2half2_rn(v.z, v.w);
        uint2 u;
        u.x = *reinterpret_cast<uint32_t*>(&h0);
        u.y = *reinterpret_cast<uint32_t*>(&h1);
        g_f0[j] = u;
    }
}

// ---------------- degree count + per-edge dst rank ----------------------------
__global__ void k_deg(const int4* __restrict__ src4, const int4* __restrict__ dst4) {
    int e = blockIdx.x * blockDim.x + threadIdx.x;
    if (e < NE / 4) {
        int4 s = src4[e];
        int4 d = dst4[e];
        atomicAdd(&g_outdeg[s.x], 1); atomicAdd(&g_outdeg[s.y], 1);
        atomicAdd(&g_outdeg[s.z], 1); atomicAdd(&g_outdeg[s.w], 1);
        int4 r;
        r.x = atomicAdd(&g_indeg[d.x], 1);
        r.y = atomicAdd(&g_indeg[d.y], 1);
        r.z = atomicAdd(&g_indeg[d.z], 1);
        r.w = atomicAdd(&g_indeg[d.w], 1);
        ((int4*)g_rank)[e] = r;
    }
}

// exclusive scan of g_indeg: per-block scan + blocksums
__global__ void k_scan1() {
    __shared__ int sh[1024];
    int t = threadIdx.x;
    int i = blockIdx.x * 1024 + t;
    int v = (i < NN) ? g_indeg[i] : 0;
    sh[t] = v;
    __syncthreads();
    #pragma unroll
    for (int off = 1; off < 1024; off <<= 1) {
        int add = (t >= off) ? sh[t - off] : 0;
        __syncthreads();
        sh[t] += add;
        __syncthreads();
    }
    if (i < NN) g_rowstart[i] = sh[t] - v;  // exclusive within block
    if (t == 1023) g_blocksums[blockIdx.x] = sh[1023];
}

// apply block offsets + compute norms (Hillis-Steele over blocksums)
__global__ void k_scan23() {
    __shared__ int sh[128];
    int t = threadIdx.x;
    int v = (t < SCAN_NB) ? g_blocksums[t] : 0;
    if (t < 128) sh[t] = v;
    __syncthreads();
    #pragma unroll
    for (int off = 1; off < 128; off <<= 1) {
        int add = (t < 128 && t >= off) ? sh[t - off] : 0;
        __syncthreads();
        if (t < 128) sh[t] += add;
        __syncthreads();
    }
    int i = blockIdx.x * blockDim.x + t;
    if (i < NN) {
        int b = i >> 10;
        int pre = (b > 0) ? sh[b - 1] : 0;
        g_rowstart[i] += pre;
        g_ns[i] = rsqrtf(fmaxf((float)g_outdeg[i], 1.0f));
        g_nd[i] = rsqrtf(fmaxf((float)g_indeg[i], 1.0f));
    }
    if (i == 0) g_rowstart[NN] = NE;
}

// atomic-free CSR fill: pos = rowstart[dst] + rank
__global__ void k_csr(const int4* __restrict__ src4, const int4* __restrict__ dst4) {
    int e = blockIdx.x * blockDim.x + threadIdx.x;
    if (e < NE / 4) {
        int4 s = src4[e];
        int4 d = dst4[e];
        int4 r = ((const int4*)g_rank)[e];
        g_csr[g_rowstart[d.x] + r.x] = s.x;
        g_csr[g_rowstart[d.y] + r.y] = s.y;
        g_csr[g_rowstart[d.z] + r.z] = s.z;
        g_csr[g_rowstart[d.w] + r.w] = s.w;
    }
}

// ---------------- SpMM: warp per node, fp16 gather, dual fp32 accum -----------
__device__ __forceinline__ void acc_edge(uint2 u, float n, float* a1, float* a2) {
    float2 f0 = __half22float2(*reinterpret_cast<__half2*>(&u.x));
    float2 f1 = __half22float2(*reinterpret_cast<__half2*>(&u.y));
    a2[0] += f0.x; a2[1] += f0.y; a2[2] += f1.x; a2[3] += f1.y;
    a1[0] = fmaf(f0.x, n, a1[0]); a1[1] = fmaf(f0.y, n, a1[1]);
    a1[2] = fmaf(f1.x, n, a1[2]); a1[3] = fmaf(f1.y, n, a1[3]);
}

__global__ __launch_bounds__(256) void k_spmm(const uint2* __restrict__ x) {
    int w    = (blockIdx.x * 256 + threadIdx.x) >> 5;
    int lane = threadIdx.x & 31;
    if (w >= NN) return;
    int s = g_rowstart[w];
    int e = g_rowstart[w + 1];
    float a1[4] = {0.f, 0.f, 0.f, 0.f};
    float a2[4] = {0.f, 0.f, 0.f, 0.f};
    int p = s;
    for (; p + 7 < e; p += 8) {
        int   j[8];
        float n[8];
        uint2 u[8];
        #pragma unroll
        for (int q = 0; q < 8; ++q) j[q] = g_csr[p + q];
        #pragma unroll
        for (int q = 0; q < 8; ++q) n[q] = g_ns[j[q]];
        #pragma unroll
        for (int q = 0; q < 8; ++q) u[q] = x[(size_t)j[q] * 32 + lane];
        #pragma unroll
        for (int q = 0; q < 8; ++q) acc_edge(u[q], n[q], a1, a2);
    }
    for (; p < e; ++p) {
        int j0 = g_csr[p];
        float n0 = g_ns[j0];
        uint2 u0 = x[(size_t)j0 * 32 + lane];
        acc_edge(u0, n0, a1, a2);
    }
    float nd = g_nd[w];
    __half2 p0 = __floats2half2_rn(a1[0] * nd, a1[1] * nd);
    __half2 p1 = __floats2half2_rn(a1[2] * nd, a1[3] * nd);
    __half2 p2 = __floats2half2_rn(a2[0], a2[1]);
    __half2 p3 = __floats2half2_rn(a2[2], a2[3]);
    uint2 o1, o2;
    o1.x = *reinterpret_cast<uint32_t*>(&p0);
    o1.y = *reinterpret_cast<uint32_t*>(&p1);
    o2.x = *reinterpret_cast<uint32_t*>(&p2);
    o2.y = *reinterpret_cast<uint32_t*>(&p3);
    uint2* yp = (uint2*)g_yh;
    yp[(size_t)w * 64 + lane]      = o1;   // halves [lane*4 .. )
    yp[(size_t)w * 64 + 32 + lane] = o2;   // halves [128 + lane*4 .. )
}

// ---------------- GEMM: C[M,BN] = A[M,256] @ Bt[BN,256]^T + bias (fp16 mma) ---
// A (g_yh) and Bt (transposed weights) are fp16 row-major. Double-buffered
// cp.async over BK=64-half chunks. 256 threads, warp grid 4m x 2n.
template <int BN, bool RELU, bool HALFOUT>
__global__ __launch_bounds__(256) void k_gemm(
    const uint32_t* __restrict__ A, const uint32_t* __restrict__ Bw,
    const float* __restrict__ bias, void* __restrict__ Cv)
{
    constexpr int BM = 128, K = 256;       // halves
    constexpr int AS = 36;                 // stage row stride in words (64h + pad)
    constexpr int ASTG = BM * AS;          // words per A stage
    constexpr int BSTG = BN * AS;          // words per B stage
    constexpr int NT = BN / 16;            // n-tiles per warp (warp n-span BN/2)
    constexpr int NKC = 4;                 // 256 / 64 chunks

    extern __shared__ uint32_t dyn[];
    uint32_t* sA = dyn;                    // 2 * ASTG
    uint32_t* sB = dyn + 2 * ASTG;         // 2 * BSTG
    const uint32_t saddrA = (uint32_t)__cvta_generic_to_shared(sA);
    const uint32_t saddrB = (uint32_t)__cvta_generic_to_shared(sB);

    const int tid  = threadIdx.x;
    const int warp = tid >> 5, lane = tid & 31;
    const int grp  = lane >> 2, tig = lane & 3;
    const int wm   = (warp >> 1) * 32;
    const int wn   = (warp & 1) * (BN / 2);
    const int blockRow = blockIdx.x * BM;

    auto stage = [&](int kc, int buf) {
        #pragma unroll
        for (int it = 0; it < 4; ++it) {       // A chunk: 128 rows x 64 halves
            int idx = tid + it * 256;          // 0..1023
            int r = idx >> 3, c = idx & 7;     // c: 8-half (4-word) units
            cp16(saddrA + (uint32_t)(buf * ASTG + r * AS + c * 4) * 4,
                 A + (size_t)(blockRow + r) * 128 + kc * 32 + c * 4);
        }
        #pragma unroll
        for (int it = 0; it < BN / 32; ++it) { // B chunk: BN rows x 64 halves
            int idx = tid + it * 256;
            int r = idx >> 3, c = idx & 7;
            cp16(saddrB + (uint32_t)(buf * BSTG + r * AS + c * 4) * 4,
                 Bw + (size_t)r * 128 + kc * 32 + c * 4);
        }
        cpcommit();
    };

    float acc[2][NT][4];
    #pragma unroll
    for (int mt = 0; mt < 2; mt++)
        #pragma unroll
        for (int nt = 0; nt < NT; nt++)
            #pragma unroll
            for (int r = 0; r < 4; r++) acc[mt][nt][r] = 0.f;

    stage(0, 0);
    #pragma unroll
    for (int kc = 0; kc < NKC; ++kc) {
        int buf = kc & 1;
        if (kc + 1 < NKC) {
            stage(kc + 1, buf ^ 1);
            cpwait<1>();
        } else {
            cpwait<0>();
        }
        __syncthreads();

        const uint32_t* cA = sA + buf * ASTG;
        const uint32_t* cB = sB + buf * BSTG;
        #pragma unroll
        for (int ks = 0; ks < 4; ++ks) {       // 4 x k16 per 64-half chunk
            uint32_t af[2][4];
            #pragma unroll
            for (int mt = 0; mt < 2; mt++) {
                int row = wm + mt * 16 + grp;
                int ko = ks * 8 + tig;          // word offset within stage row
                af[mt][0] = cA[row * AS + ko];
                af[mt][1] = cA[(row + 8) * AS + ko];
                af[mt][2] = cA[row * AS + ko + 4];
                af[mt][3] = cA[(row + 8) * AS + ko + 4];
            }
            uint32_t bf[NT][2];
            #pragma unroll
            for (int nt = 0; nt < NT; nt++) {
                int col = wn + nt * 8 + grp;
                int ko = ks * 8 + tig;
                bf[nt][0] = cB[col * AS + ko];
                bf[nt][1] = cB[col * AS + ko + 4];
            }
            #pragma unroll
            for (int mt = 0; mt < 2; mt++)
                #pragma unroll
                for (int nt = 0; nt < NT; nt++)
                    mma_f16(acc[mt][nt], af[mt], bf[nt]);
        }
        __syncthreads();
    }

    // epilogue: bias (+relu), half2 or float2 stores
    #pragma unroll
    for (int mt = 0; mt < 2; ++mt) {
        int r0 = blockRow + wm + mt * 16 + grp;
        int r1 = r0 + 8;
        #pragma unroll
        for (int nt = 0; nt < NT; ++nt) {
            int col = wn + nt * 8 + 2 * tig;
            float b0v = bias[col], b1v = bias[col + 1];
            float v0 = acc[mt][nt][0] + b0v;
            float v1 = acc[mt][nt][1] + b1v;
            float v2 = acc[mt][nt][2] + b0v;
            float v3 = acc[mt][nt][3] + b1v;
            if (RELU) {
                v0 = fmaxf(v0, 0.f); v1 = fmaxf(v1, 0.f);
                v2 = fmaxf(v2, 0.f); v3 = fmaxf(v3, 0.f);
            }
            if (HALFOUT) {
                __half* C = (__half*)Cv;
                if (r0 < NN)
                    *reinterpret_cast<__half2*>(&C[(size_t)r0 * BN + col]) =
                        __floats2half2_rn(v0, v1);
                if (r1 < NN)
                    *reinterpret_cast<__half2*>(&C[(size_t)r1 * BN + col]) =
                        __floats2half2_rn(v2, v3);
            } else {
                float* C = (float*)Cv;
                if (r0 < NN)
                    *reinterpret_cast<float2*>(&C[(size_t)r0 * BN + col]) = make_float2(v0, v1);
                if (r1 < NN)
                    *reinterpret_cast<float2*>(&C[(size_t)r1 * BN + col]) = make_float2(v2, v3);
            }
        }
    }
}

// ---------------- launcher ----------------------------------------------------
extern "C" void kernel_launch(void* const* d_in, const int* in_sizes, int n_in,
                              void* d_out, int out_size) {
    const float* raw_x = (const float*)d_in[0];
    const int*   src   = (const int*)d_in[1];
    const int*   dst   = (const int*)d_in[2];
    const float* w0    = (const float*)d_in[3];
    const float* b0    = (const float*)d_in[4];
    const float* w1    = (const float*)d_in[5];
    const float* b1    = (const float*)d_in[6];
    const float* w2    = (const float*)d_in[7];
    const float* b2    = (const float*)d_in[8];
    const float* rw0   = (const float*)d_in[9];
    const float* rw1   = (const float*)d_in[10];
    const float* rw2   = (const float*)d_in[11];
    float* out = (float*)d_out;

    void *py = nullptr, *pf0 = nullptr, *pf1 = nullptr;
    void *pw0 = nullptr, *pw1 = nullptr, *pw2 = nullptr;
    cudaGetSymbolAddress(&py, g_yh);
    cudaGetSymbolAddress(&pf0, g_f0);
    cudaGetSymbolAddress(&pf1, g_f1);
    cudaGetSymbolAddress(&pw0, g_wt0);
    cudaGetSymbolAddress(&pw1, g_wt1);
    cudaGetSymbolAddress(&pw2, g_wt2);

    constexpr int SMEM128 = 2 * (128 * 36 + 128 * 36) * 4;  // 73728
    constexpr int SMEM64  = 2 * (128 * 36 + 64 * 36) * 4;   // 55296
    cudaFuncSetAttribute(k_gemm<128, true, true>,
                         cudaFuncAttributeMaxDynamicSharedMemorySize, SMEM128);
    cudaFuncSetAttribute(k_gemm<64, false, false>,
                         cudaFuncAttributeMaxDynamicSharedMemorySize, SMEM64);

    const int TB = 256;
    k_prep<<<(3331920 + TB - 1) / TB, TB>>>((const float4*)raw_x,
                                            w0, rw0, w1, rw1, w2, rw2);
    k_deg<<<(NE / 4 + TB - 1) / TB, TB>>>((const int4*)src, (const int4*)dst);
    k_scan1<<<SCAN_NB, 1024>>>();
    k_scan23<<<(NN + TB - 1) / TB, TB>>>();
    k_csr<<<(NE / 4 + TB - 1) / TB, TB>>>((const int4*)src, (const int4*)dst);

    const int SPMM_BLOCKS = (NN * 32 + TB - 1) / TB;  // one warp per node
    const int GEMM_BLOCKS = NN_PAD / 128;             // 782

    // layer 1: spmm(g_f0=x) -> g_yh ; gemm -> g_f1 (h1, fp16)
    k_spmm<<<SPMM_BLOCKS, TB>>>((const uint2*)pf0);
    k_gemm<128, true, true><<<GEMM_BLOCKS, TB, SMEM128>>>(
        (const uint32_t*)py, (const uint32_t*)pw0, b0, pf1);
    // layer 2: spmm(g_f1) -> g_yh ; gemm -> g_f0 (h2, fp16)
    k_spmm<<<SPMM_BLOCKS, TB>>>((const uint2*)pf1);
    k_gemm<128, true, true><<<GEMM_BLOCKS, TB, SMEM128>>>(
        (const uint32_t*)py, (const uint32_t*)pw1, b1, pf0);
    // layer 3: spmm(g_f0) -> g_yh ; gemm -> d_out (fp32)
    k_spmm<<<SPMM_BLOCKS, TB>>>((const uint2*)pf0);
    k_gemm<64, false, false><<<GEMM_BLOCKS, TB, SMEM64>>>(
        (const uint32_t*)py, (const uint32_t*)pw2, b2, out);
}